// round 1
// baseline (speedup 1.0000x reference)
#include <cuda_runtime.h>
#include <math.h>

#define DH      128
#define NMAXN   20000
#define EMAXE   320000
#define LN_EPS  1e-5f

// ---------------- device scratch (no allocs allowed) ----------------
__device__ float g_h  [NMAXN*DH];
__device__ float g_hh [NMAXN*DH];
__device__ float g_hc [NMAXN*DH];
__device__ float g_hn [NMAXN*DH];
__device__ float g_tmp[NMAXN*DH];
__device__ float g_acc[NMAXN*DH];
__device__ float g_dis[NMAXN];
__device__ float g_wsort[EMAXE];
__device__ int   g_cnt[NMAXN];
__device__ int   g_cur[NMAXN];
__device__ int   g_off[NMAXN+1];
__device__ int   g_srt[EMAXE];
__device__ float g_dt;
__device__ float g_escale;

// ---------------- helpers ----------------
__device__ __forceinline__ float blockReduce128(float v) {
    #pragma unroll
    for (int o = 16; o > 0; o >>= 1) v += __shfl_down_sync(0xffffffffu, v, o);
    __shared__ float sh[4];
    if ((threadIdx.x & 31) == 0) sh[threadIdx.x >> 5] = v;
    __syncthreads();
    float r = sh[0] + sh[1] + sh[2] + sh[3];
    __syncthreads();
    return r;
}

// ---------------- graph preprocessing ----------------
__global__ void k_zero_cnt(int n) {
    int i = blockIdx.x * blockDim.x + threadIdx.x;
    if (i < n) { g_cnt[i] = 0; g_cur[i] = 0; }
}

__global__ void k_deg(const int* __restrict__ col, int E) {
    int e = blockIdx.x * blockDim.x + threadIdx.x;
    if (e < E) atomicAdd(&g_cnt[col[e]], 1);
}

__global__ void k_dis(int n) {
    int i = blockIdx.x * blockDim.x + threadIdx.x;
    if (i < n) {
        int c = g_cnt[i];
        g_dis[i] = (c > 0) ? rsqrtf((float)c) : 0.0f;
    }
}

// single-block inclusive scan over counts -> offsets
__global__ void k_scan(int n) {
    __shared__ int sh[1024];
    int tid = threadIdx.x;
    int carry = 0;
    if (tid == 0) g_off[0] = 0;
    for (int base = 0; base < n; base += 1024) {
        int i = base + tid;
        int v = (i < n) ? g_cnt[i] : 0;
        sh[tid] = v;
        __syncthreads();
        for (int o = 1; o < 1024; o <<= 1) {
            int t = (tid >= o) ? sh[tid - o] : 0;
            __syncthreads();
            sh[tid] += t;
            __syncthreads();
        }
        if (i < n) g_off[i + 1] = carry + sh[tid];
        carry += sh[1023];
        __syncthreads();
    }
}

__global__ void k_scatter(const int* __restrict__ row, const int* __restrict__ col, int E) {
    int e = blockIdx.x * blockDim.x + threadIdx.x;
    if (e >= E) return;
    int c = col[e];
    int r = row[e];
    int pos = g_off[c] + atomicAdd(&g_cur[c], 1);
    g_srt[pos]   = r;
    g_wsort[pos] = g_dis[r] * g_dis[c];
}

__global__ void k_scalars(const float* __restrict__ meth,
                          const float* __restrict__ hist,
                          const float* __restrict__ logd) {
    float v = 1.0f / (1.0f + expf(-meth[threadIdx.x]));
    float s = blockReduce128(v) * (1.0f / 128.0f);
    if (threadIdx.x == 0) {
        float hs0 = 1.0f / (1.0f + expf(-hist[0]));
        float hs1 = 1.0f / (1.0f + expf(-hist[1]));
        float hs2 = 1.0f / (1.0f + expf(-hist[2]));
        float hs3 = 1.0f / (1.0f + expf(-hist[3]));
        float act = 0.5f * (hs0 + hs2);
        float rep = 0.5f * (hs1 + hs3);
        float access = fminf(fmaxf(act - rep + 0.5f, 0.0f), 1.0f);
        g_escale = access * (1.0f - s);
        float depth = fminf(fmaxf(expf(logd[0]), 0.1f), 3.0f);
        g_dt = depth / 19.0f;
    }
}

// ---------------- dense matmul: C[N x 128] = A[N x K] @ W[K x 128] ----------------
// mode 0: C = acc + bias (bias may be null)
// mode 1: gate epilogue: g = sigmoid(acc + bias); C = g*A2 + (1-g)*A  (C aliases A)
// A2 supplies k >= 128 for K=256 (concat).
#define MM_BM 64
#define MM_BK 32
__global__ void mm_kernel(const float* __restrict__ A, const float* __restrict__ A2,
                          const float* __restrict__ W, const float* __restrict__ bias,
                          float* __restrict__ C, int N, int K, int lda, int mode) {
    __shared__ float As[MM_BM * MM_BK];
    __shared__ float Ws[MM_BK * 128];
    int row0 = blockIdx.x * MM_BM;
    int tx = threadIdx.x & 31;   // 32 column groups of 4
    int ty = threadIdx.x >> 5;   // 8 row groups of 8
    float acc[8][4];
    #pragma unroll
    for (int j = 0; j < 8; j++) { acc[j][0]=0.f; acc[j][1]=0.f; acc[j][2]=0.f; acc[j][3]=0.f; }

    for (int kk = 0; kk < K; kk += MM_BK) {
        // load A tile (64 x 32)
        for (int l = threadIdx.x; l < MM_BM * MM_BK; l += 256) {
            int r = l >> 5, k = l & 31;
            int gr = row0 + r, gk = kk + k;
            float v = 0.0f;
            if (gr < N) {
                if (gk < 128 || A2 == nullptr) v = A[gr * lda + gk];
                else                           v = A2[gr * 128 + (gk - 128)];
            }
            As[l] = v;
        }
        // load W tile (32 x 128)
        for (int l = threadIdx.x; l < MM_BK * 128; l += 256) {
            Ws[l] = W[(kk + (l >> 7)) * 128 + (l & 127)];
        }
        __syncthreads();
        #pragma unroll
        for (int k = 0; k < MM_BK; k++) {
            float4 wv = *(const float4*)(&Ws[k * 128 + tx * 4]);
            #pragma unroll
            for (int j = 0; j < 8; j++) {
                float a = As[(ty * 8 + j) * MM_BK + k];
                acc[j][0] += a * wv.x;
                acc[j][1] += a * wv.y;
                acc[j][2] += a * wv.z;
                acc[j][3] += a * wv.w;
            }
        }
        __syncthreads();
    }

    int c0 = tx * 4;
    float4 bv = make_float4(0.f, 0.f, 0.f, 0.f);
    if (bias) bv = *(const float4*)(&bias[c0]);
    #pragma unroll
    for (int j = 0; j < 8; j++) {
        int r = row0 + ty * 8 + j;
        if (r >= N) break;
        if (mode == 0) {
            float4 o;
            o.x = acc[j][0] + bv.x; o.y = acc[j][1] + bv.y;
            o.z = acc[j][2] + bv.z; o.w = acc[j][3] + bv.w;
            *(float4*)(&C[r * 128 + c0]) = o;
        } else {
            float4 av = *(const float4*)(&A [r * 128 + c0]);
            float4 nv = *(const float4*)(&A2[r * 128 + c0]);
            float l0 = acc[j][0] + bv.x, l1 = acc[j][1] + bv.y;
            float l2 = acc[j][2] + bv.z, l3 = acc[j][3] + bv.w;
            float s0 = 1.0f / (1.0f + expf(-l0));
            float s1 = 1.0f / (1.0f + expf(-l1));
            float s2 = 1.0f / (1.0f + expf(-l2));
            float s3 = 1.0f / (1.0f + expf(-l3));
            float4 o;
            o.x = s0 * nv.x + (1.0f - s0) * av.x;
            o.y = s1 * nv.y + (1.0f - s1) * av.y;
            o.z = s2 * nv.z + (1.0f - s2) * av.z;
            o.w = s3 * nv.w + (1.0f - s3) * av.w;
            *(float4*)(&C[r * 128 + c0]) = o;
        }
    }
}

// ---------------- per-node aggregation (CSR) + bias + LayerNorm ----------------
__global__ void agg_ln_kernel(const float* __restrict__ tmp,
                              const float* __restrict__ bias,
                              const float* __restrict__ gamma,
                              const float* __restrict__ beta,
                              float* __restrict__ out) {
    int n = blockIdx.x;
    int c = threadIdx.x;                 // 128 threads
    int s = g_off[n], e = g_off[n + 1];
    float acc = bias[c];
    __shared__ int   ssrc[128];
    __shared__ float sw[128];
    for (int base = s; base < e; base += 128) {
        int m = min(128, e - base);
        if (c < m) { ssrc[c] = g_srt[base + c]; sw[c] = g_wsort[base + c]; }
        __syncthreads();
        #pragma unroll 4
        for (int j = 0; j < m; j++)
            acc += tmp[ssrc[j] * 128 + c] * sw[j];
        __syncthreads();
    }
    float mu = blockReduce128(acc) * (1.0f / 128.0f);
    float d = acc - mu;
    float var = blockReduce128(d * d) * (1.0f / 128.0f);
    out[n * 128 + c] = d * rsqrtf(var + LN_EPS) * gamma[c] + beta[c];
}

// ---------------- input projection epilogue: relu(LN(.)) * escale -> g_h ----------------
__global__ void k_ln_relu_scale(const float* __restrict__ tmp,
                                const float* __restrict__ gamma,
                                const float* __restrict__ beta) {
    int n = blockIdx.x, c = threadIdx.x;
    float v = tmp[n * 128 + c];
    float mu = blockReduce128(v) * (1.0f / 128.0f);
    float d = v - mu;
    float var = blockReduce128(d * d) * (1.0f / 128.0f);
    float y = d * rsqrtf(var + LN_EPS) * gamma[c] + beta[c];
    g_h[n * 128 + c] = fmaxf(y, 0.0f) * g_escale;
}

// ---------------- RK4 stage combine ----------------
// k = tanh(hc) + res_w * fin ; accumulate and produce next f input / state update
__global__ void k_rk_stage(const float* __restrict__ hc, const float* __restrict__ fin,
                           const float* __restrict__ res_w, int stage, int total) {
    int i = blockIdx.x * blockDim.x + threadIdx.x;
    if (i >= total) return;
    float k = tanhf(hc[i]) + res_w[0] * fin[i];
    float dt = g_dt;
    if (stage == 0)      { g_acc[i] = k;            g_hh[i] = g_h[i] + 0.5f * dt * k; }
    else if (stage == 1) { g_acc[i] += 2.0f * k;    g_hh[i] = g_h[i] + 0.5f * dt * k; }
    else if (stage == 2) { g_acc[i] += 2.0f * k;    g_hh[i] = g_h[i] + dt * k; }
    else                 { g_h[i]  += (dt / 6.0f) * (g_acc[i] + k); }
}

// ---------------- output: LN per row then mean over nodes ----------------
__global__ void k_zero_out(float* out) { out[threadIdx.x] = 0.0f; }

__global__ void k_out_reduce(const float* __restrict__ tmp,
                             const float* __restrict__ gamma,
                             const float* __restrict__ beta,
                             float* __restrict__ out, int N) {
    int c = threadIdx.x;
    int r0 = blockIdx.x * 64;
    float partial = 0.0f;
    for (int r = r0; r < r0 + 64; r++) {
        if (r >= N) break;
        float v = tmp[r * 128 + c];
        float mu = blockReduce128(v) * (1.0f / 128.0f);
        float d = v - mu;
        float var = blockReduce128(d * d) * (1.0f / 128.0f);
        partial += d * rsqrtf(var + LN_EPS) * gamma[c] + beta[c];
    }
    atomicAdd(&out[c], partial / (float)N);
}

// ---------------- host orchestration ----------------
extern "C" void kernel_launch(void* const* d_in, const int* in_sizes, int n_in,
                              void* d_out, int out_size) {
    const float* x        = (const float*)d_in[0];
    const int*   ei       = (const int*)  d_in[1];
    const float* Wi       = (const float*)d_in[2];
    const float* bi       = (const float*)d_in[3];
    const float* ln_in_g  = (const float*)d_in[4];
    const float* ln_in_b  = (const float*)d_in[5];
    const float* meth     = (const float*)d_in[6];
    const float* hist     = (const float*)d_in[7];
    const float* gcn_w    = (const float*)d_in[8];
    const float* gcn_b    = (const float*)d_in[9];
    const float* ln_g     = (const float*)d_in[10];
    const float* ln_b     = (const float*)d_in[11];
    const float* gate_w   = (const float*)d_in[12];
    const float* gate_b   = (const float*)d_in[13];
    const float* res_w    = (const float*)d_in[14];
    const float* log_d    = (const float*)d_in[15];
    const float* Wo       = (const float*)d_in[16];
    const float* bo       = (const float*)d_in[17];
    const float* ln_out_g = (const float*)d_in[18];
    const float* ln_out_b = (const float*)d_in[19];
    float* out = (float*)d_out;

    int N = in_sizes[0] / 64;   // 20000
    int E = in_sizes[1] / 2;    // 320000
    const int* e_row = ei;
    const int* e_col = ei + E;

    float *p_h, *p_hh, *p_hc, *p_hn, *p_tmp;
    cudaGetSymbolAddress((void**)&p_h,  g_h);
    cudaGetSymbolAddress((void**)&p_hh, g_hh);
    cudaGetSymbolAddress((void**)&p_hc, g_hc);
    cudaGetSymbolAddress((void**)&p_hn, g_hn);
    cudaGetSymbolAddress((void**)&p_tmp,g_tmp);

    int gb = (N + MM_BM - 1) / MM_BM;       // matmul blocks
    int total = N * DH;
    int eg = (E + 255) / 256;
    int ng = (N + 255) / 256;

    // --- graph preprocessing (every replay; cheap) ---
    k_zero_cnt<<<ng, 256>>>(N);
    k_deg<<<eg, 256>>>(e_col, E);
    k_dis<<<ng, 256>>>(N);
    k_scan<<<1, 1024>>>(N);
    k_scatter<<<eg, 256>>>(e_row, e_col, E);
    k_scalars<<<1, 128>>>(meth, hist, log_d);

    // --- input projection: h = relu(LN(x@Wi + bi)) * escale ---
    mm_kernel<<<gb, 256>>>(x, nullptr, Wi, bi, p_tmp, N, 64, 64, 0);
    k_ln_relu_scale<<<N, 128>>>(p_tmp, ln_in_g, ln_in_b);

    // --- 19 RK4 steps, 4 f-evals each ---
    for (int step = 0; step < 19; step++) {
        for (int st = 0; st < 4; st++) {
            const float* fin = (st == 0) ? p_h : p_hh;
            // GCN layer 0
            mm_kernel<<<gb, 256>>>(fin, nullptr, gcn_w, nullptr, p_tmp, N, 128, 128, 0);
            agg_ln_kernel<<<N, 128>>>(p_tmp, gcn_b, ln_g, ln_b, p_hc);
            // GCN layer 1 + gate
            mm_kernel<<<gb, 256>>>(p_hc, nullptr, gcn_w + 128*128, nullptr, p_tmp, N, 128, 128, 0);
            agg_ln_kernel<<<N, 128>>>(p_tmp, gcn_b + 128, ln_g + 128, ln_b + 128, p_hn);
            mm_kernel<<<gb, 256>>>(p_hc, p_hn, gate_w, gate_b, p_hc, N, 256, 128, 1);
            // GCN layer 2 + gate
            mm_kernel<<<gb, 256>>>(p_hc, nullptr, gcn_w + 2*128*128, nullptr, p_tmp, N, 128, 128, 0);
            agg_ln_kernel<<<N, 128>>>(p_tmp, gcn_b + 256, ln_g + 256, ln_b + 256, p_hn);
            mm_kernel<<<gb, 256>>>(p_hc, p_hn, gate_w, gate_b, p_hc, N, 256, 128, 1);
            // stage combine
            k_rk_stage<<<(total + 255) / 256, 256>>>(p_hc, fin, res_w, st, total);
        }
    }

    // --- output projection + LN + global mean pool ---
    mm_kernel<<<gb, 256>>>(p_h, nullptr, Wo, bo, p_tmp, N, 128, 128, 0);
    k_zero_out<<<1, 128>>>(out);
    k_out_reduce<<<(N + 63) / 64, 128>>>(p_tmp, ln_out_g, ln_out_b, out, N);
}

// round 3
// speedup vs baseline: 1.4245x; 1.4245x over previous
#include <cuda_runtime.h>
#include <cuda_bf16.h>
#include <math.h>
#include <stdint.h>

#define DH      128
#define NMAXN   20000
#define EMAXE   320000
#define LN_EPS  1e-5f

// ---------------- device scratch (no allocs allowed) ----------------
__device__ float g_h  [NMAXN*DH];
__device__ float g_hh [NMAXN*DH];
__device__ float g_hc [NMAXN*DH];
__device__ float g_hn [NMAXN*DH];
__device__ float g_tmp[NMAXN*DH];
__device__ float g_acc[NMAXN*DH];
__device__ float g_dis[NMAXN];
__device__ float g_wsort[EMAXE];
__device__ int   g_cnt[NMAXN];
__device__ int   g_cur[NMAXN];
__device__ int   g_off[NMAXN+1];
__device__ int   g_srt[EMAXE];
__device__ float g_dt;
__device__ float g_escale;

// ---------------- helpers ----------------
__device__ __forceinline__ float blockReduce128(float v) {
    #pragma unroll
    for (int o = 16; o > 0; o >>= 1) v += __shfl_down_sync(0xffffffffu, v, o);
    __shared__ float sh[4];
    if ((threadIdx.x & 31) == 0) sh[threadIdx.x >> 5] = v;
    __syncthreads();
    float r = sh[0] + sh[1] + sh[2] + sh[3];
    __syncthreads();
    return r;
}

__device__ __forceinline__ uint32_t smem_u32(const void* p) {
    uint32_t a;
    asm("{ .reg .u64 t; cvta.to.shared.u64 t, %1; cvt.u32.u64 %0, t; }" : "=r"(a) : "l"(p));
    return a;
}

// ---------------- graph preprocessing ----------------
__global__ void k_zero_cnt(int n) {
    int i = blockIdx.x * blockDim.x + threadIdx.x;
    if (i < n) { g_cnt[i] = 0; g_cur[i] = 0; }
}
__global__ void k_deg(const int* __restrict__ col, int E) {
    int e = blockIdx.x * blockDim.x + threadIdx.x;
    if (e < E) atomicAdd(&g_cnt[col[e]], 1);
}
__global__ void k_dis(int n) {
    int i = blockIdx.x * blockDim.x + threadIdx.x;
    if (i < n) {
        int c = g_cnt[i];
        g_dis[i] = (c > 0) ? rsqrtf((float)c) : 0.0f;
    }
}
// register-blocked scan: 1024 threads, each owns a contiguous chunk
__global__ void k_scan(int n) {
    __shared__ int sh[1024];
    int tid = threadIdx.x;
    int PER = (n + 1023) >> 10;
    if (PER > 32) PER = 32;
    int start = tid * PER;
    int local[32];
    int sum = 0;
    for (int j = 0; j < PER; j++) {
        int i = start + j;
        int v = (i < n) ? g_cnt[i] : 0;
        local[j] = v; sum += v;
    }
    sh[tid] = sum;
    __syncthreads();
    for (int o = 1; o < 1024; o <<= 1) {
        int t = (tid >= o) ? sh[tid - o] : 0;
        __syncthreads();
        sh[tid] += t;
        __syncthreads();
    }
    int run = (tid > 0) ? sh[tid - 1] : 0;
    for (int j = 0; j < PER; j++) {
        int i = start + j;
        run += local[j];
        if (i < n) g_off[i + 1] = run;
    }
    if (tid == 0) g_off[0] = 0;
}
__global__ void k_scatter(const int* __restrict__ row, const int* __restrict__ col, int E) {
    int e = blockIdx.x * blockDim.x + threadIdx.x;
    if (e >= E) return;
    int c = col[e];
    int r = row[e];
    int pos = g_off[c] + atomicAdd(&g_cur[c], 1);
    g_srt[pos]   = r;
    g_wsort[pos] = g_dis[r] * g_dis[c];
}
__global__ void k_scalars(const float* __restrict__ meth,
                          const float* __restrict__ hist,
                          const float* __restrict__ logd) {
    float v = 1.0f / (1.0f + expf(-meth[threadIdx.x]));
    float s = blockReduce128(v) * (1.0f / 128.0f);
    if (threadIdx.x == 0) {
        float hs0 = 1.0f / (1.0f + expf(-hist[0]));
        float hs1 = 1.0f / (1.0f + expf(-hist[1]));
        float hs2 = 1.0f / (1.0f + expf(-hist[2]));
        float hs3 = 1.0f / (1.0f + expf(-hist[3]));
        float act = 0.5f * (hs0 + hs2);
        float rep = 0.5f * (hs1 + hs3);
        float access = fminf(fmaxf(act - rep + 0.5f, 0.0f), 1.0f);
        g_escale = access * (1.0f - s);
        float depth = fminf(fmaxf(expf(logd[0]), 0.1f), 3.0f);
        g_dt = depth / 19.0f;
    }
}

// ---------------- bf16x3 mma.sync GEMM ----------------
// C[N x 128] = A[N x K] @ W[K x 128]; K in {64,128,256}.
// K=256: pass0 uses A, pass1 uses A2 (concat halves), register accumulation.
// mode 0: C = D + bias
// mode 1: g = sigmoid(D + bias); C = g*A2 + (1-g)*A
// mode 2: mode1 blend (not stored) -> fused RK4 stage combine (stage param)
#define TM     256
#define TN     128
#define LDA_S  136            // halves per row (128 + 8 pad)
#define SM_BIAS 0
#define SM_A_HI 512
#define SM_A_LO (512 + 69632)
#define SM_W_HI (512 + 2*69632)
#define SM_W_LO (512 + 2*69632 + 34816)
#define SMM_BYTES (512 + 2*69632 + 2*34816)   // 209920

__device__ __forceinline__ void cvt_pair(float x0, float x1, uint32_t& hi, uint32_t& lo) {
    __nv_bfloat16 h0 = __float2bfloat16(x0);
    __nv_bfloat16 h1 = __float2bfloat16(x1);
    __nv_bfloat162 hv; hv.x = h0; hv.y = h1;
    __nv_bfloat162 lv;
    lv.x = __float2bfloat16(x0 - __bfloat162float(h0));
    lv.y = __float2bfloat16(x1 - __bfloat162float(h1));
    hi = *(uint32_t*)&hv;
    lo = *(uint32_t*)&lv;
}

__global__ void __launch_bounds__(512, 1)
tensor_mm(const float* __restrict__ A, const float* __restrict__ A2,
          const float* __restrict__ W, const float* __restrict__ bias,
          float* __restrict__ C, int N, int K, int lda, int mode, int stage,
          const float* __restrict__ fin, const float* __restrict__ res_w) {
    extern __shared__ char smem[];
    uint32_t sb = smem_u32(smem);
    int tid = threadIdx.x;
    int w   = tid >> 5;
    int l   = tid & 31;
    int row0 = blockIdx.x * TM;

    if (tid < 128) ((float*)(smem + SM_BIAS))[tid] = bias ? bias[tid] : 0.0f;

    int mbase = (w & 3) * 64;
    int nbase = (w >> 2) * 32;

    float acc[4][4][4];
    #pragma unroll
    for (int mt = 0; mt < 4; mt++)
        #pragma unroll
        for (int nt = 0; nt < 4; nt++)
            #pragma unroll
            for (int i = 0; i < 4; i++) acc[mt][nt][i] = 0.0f;

    int passes = (K + 127) >> 7;

    // per-thread ldmatrix base offsets (in halves)
    int a_row = mbase + (l & 15);
    int a_colh = ((l >> 4) & 1) * 8;
    int b_row = (l & 15);

    for (int pass = 0; pass < passes; pass++) {
        const float* Asrc = (pass == 0) ? A : A2;
        int lda_p = (pass == 0) ? lda : 128;
        int Kt = K - pass * 128; if (Kt > 128) Kt = 128;
        int koff = pass * 128;

        __syncthreads();   // all warps done with previous tiles
        // stage A tile [256 x 128] -> bf16 hi/lo
        for (int it = tid; it < TM * 64; it += 512) {
            int r  = it >> 6;
            int kp = (it & 63) << 1;
            float x0 = 0.0f, x1 = 0.0f;
            int gr = row0 + r;
            if (gr < N && kp < Kt) {
                float2 v = *(const float2*)(Asrc + (size_t)gr * lda_p + kp);
                x0 = v.x; x1 = v.y;
            }
            uint32_t hv, lv;
            cvt_pair(x0, x1, hv, lv);
            int off = r * LDA_S + kp;
            *(uint32_t*)(smem + SM_A_HI + off * 2) = hv;
            *(uint32_t*)(smem + SM_A_LO + off * 2) = lv;
        }
        // stage W tile [128 k x 128 n] -> bf16 hi/lo (no transpose)
        for (int it = tid; it < 128 * 64; it += 512) {
            int k  = it >> 6;
            int np = (it & 63) << 1;
            float w0 = 0.0f, w1 = 0.0f;
            if (k < Kt) {
                float2 v = *(const float2*)(W + (size_t)(koff + k) * 128 + np);
                w0 = v.x; w1 = v.y;
            }
            uint32_t hv, lv;
            cvt_pair(w0, w1, hv, lv);
            int off = k * LDA_S + np;
            *(uint32_t*)(smem + SM_W_HI + off * 2) = hv;
            *(uint32_t*)(smem + SM_W_LO + off * 2) = lv;
        }
        __syncthreads();

        #pragma unroll
        for (int split = 0; split < 3; split++) {
            uint32_t Ab = sb + ((split == 2) ? SM_A_LO : SM_A_HI);
            uint32_t Wb = sb + ((split == 1) ? SM_W_LO : SM_W_HI);
            #pragma unroll
            for (int ks = 0; ks < 8; ks++) {
                int k0 = ks * 16;
                uint32_t a[4][4];
                #pragma unroll
                for (int mt = 0; mt < 4; mt++) {
                    uint32_t addr = Ab + (uint32_t)(((a_row + 16 * mt) * LDA_S + k0 + a_colh) * 2);
                    asm volatile("ldmatrix.sync.aligned.m8n8.x4.shared.b16 {%0,%1,%2,%3}, [%4];"
                                 : "=r"(a[mt][0]), "=r"(a[mt][1]), "=r"(a[mt][2]), "=r"(a[mt][3])
                                 : "r"(addr));
                }
                uint32_t b[4][2];
                #pragma unroll
                for (int nt = 0; nt < 4; nt++) {
                    uint32_t addr = Wb + (uint32_t)(((k0 + b_row) * LDA_S + nbase + 8 * nt) * 2);
                    asm volatile("ldmatrix.sync.aligned.m8n8.x2.trans.shared.b16 {%0,%1}, [%2];"
                                 : "=r"(b[nt][0]), "=r"(b[nt][1])
                                 : "r"(addr));
                }
                #pragma unroll
                for (int mt = 0; mt < 4; mt++)
                    #pragma unroll
                    for (int nt = 0; nt < 4; nt++) {
                        asm volatile(
                            "mma.sync.aligned.m16n8k16.row.col.f32.bf16.bf16.f32 "
                            "{%0,%1,%2,%3}, {%4,%5,%6,%7}, {%8,%9}, {%0,%1,%2,%3};"
                            : "+f"(acc[mt][nt][0]), "+f"(acc[mt][nt][1]),
                              "+f"(acc[mt][nt][2]), "+f"(acc[mt][nt][3])
                            : "r"(a[mt][0]), "r"(a[mt][1]), "r"(a[mt][2]), "r"(a[mt][3]),
                              "r"(b[nt][0]), "r"(b[nt][1]));
                    }
            }
        }
    }

    // ---- epilogue ----
    const float* bsm = (const float*)(smem + SM_BIAS);
    float rw = 0.0f, dt = 0.0f;
    if (mode == 2) { rw = res_w[0]; dt = g_dt; }
    #pragma unroll
    for (int mt = 0; mt < 4; mt++) {
        #pragma unroll
        for (int half = 0; half < 2; half++) {      // d0,d1 then d2,d3 (+8 rows)
            int row = row0 + mbase + 16 * mt + (l >> 2) + half * 8;
            if (row >= N) continue;
            #pragma unroll
            for (int nt = 0; nt < 4; nt++) {
                int col = nbase + 8 * nt + 2 * (l & 3);
                float d0 = acc[mt][nt][half * 2 + 0] + bsm[col];
                float d1 = acc[mt][nt][half * 2 + 1] + bsm[col + 1];
                size_t idx = (size_t)row * 128 + col;
                if (mode == 0) {
                    *(float2*)(&C[idx]) = make_float2(d0, d1);
                } else {
                    float2 av = *(const float2*)(&A [idx]);
                    float2 nv = *(const float2*)(&A2[idx]);
                    float s0 = 1.0f / (1.0f + expf(-d0));
                    float s1 = 1.0f / (1.0f + expf(-d1));
                    float o0 = s0 * nv.x + (1.0f - s0) * av.x;
                    float o1 = s1 * nv.y + (1.0f - s1) * av.y;
                    if (mode == 1) {
                        *(float2*)(&C[idx]) = make_float2(o0, o1);
                    } else {
                        float2 fv = *(const float2*)(&fin[idx]);
                        float k0v = tanhf(o0) + rw * fv.x;
                        float k1v = tanhf(o1) + rw * fv.y;
                        if (stage == 0) {
                            g_acc[idx]   = k0v;  g_acc[idx+1] = k1v;
                            g_hh[idx]    = g_h[idx]   + 0.5f * dt * k0v;
                            g_hh[idx+1]  = g_h[idx+1] + 0.5f * dt * k1v;
                        } else if (stage == 1) {
                            g_acc[idx]  += 2.0f * k0v;  g_acc[idx+1] += 2.0f * k1v;
                            g_hh[idx]    = g_h[idx]   + 0.5f * dt * k0v;
                            g_hh[idx+1]  = g_h[idx+1] + 0.5f * dt * k1v;
                        } else if (stage == 2) {
                            g_acc[idx]  += 2.0f * k0v;  g_acc[idx+1] += 2.0f * k1v;
                            g_hh[idx]    = g_h[idx]   + dt * k0v;
                            g_hh[idx+1]  = g_h[idx+1] + dt * k1v;
                        } else {
                            g_h[idx]   += (dt / 6.0f) * (g_acc[idx]   + k0v);
                            g_h[idx+1] += (dt / 6.0f) * (g_acc[idx+1] + k1v);
                        }
                    }
                }
            }
        }
    }
}

// ---------------- per-node aggregation (CSR) + bias + LayerNorm ----------------
__global__ void agg_ln_kernel(const float* __restrict__ tmp,
                              const float* __restrict__ bias,
                              const float* __restrict__ gamma,
                              const float* __restrict__ beta,
                              float* __restrict__ out) {
    int n = blockIdx.x;
    int c = threadIdx.x;                 // 128 threads
    int s = g_off[n], e = g_off[n + 1];
    float acc = bias[c];
    __shared__ int   ssrc[128];
    __shared__ float sw[128];
    for (int base = s; base < e; base += 128) {
        int m = min(128, e - base);
        if (c < m) { ssrc[c] = g_srt[base + c]; sw[c] = g_wsort[base + c]; }
        __syncthreads();
        #pragma unroll 4
        for (int j = 0; j < m; j++)
            acc += tmp[(size_t)ssrc[j] * 128 + c] * sw[j];
        __syncthreads();
    }
    float mu = blockReduce128(acc) * (1.0f / 128.0f);
    float d = acc - mu;
    float var = blockReduce128(d * d) * (1.0f / 128.0f);
    out[(size_t)n * 128 + c] = d * rsqrtf(var + LN_EPS) * gamma[c] + beta[c];
}

// ---------------- input projection epilogue: relu(LN(.)) * escale -> g_h ----------------
__global__ void k_ln_relu_scale(const float* __restrict__ tmp,
                                const float* __restrict__ gamma,
                                const float* __restrict__ beta) {
    int n = blockIdx.x, c = threadIdx.x;
    float v = tmp[(size_t)n * 128 + c];
    float mu = blockReduce128(v) * (1.0f / 128.0f);
    float d = v - mu;
    float var = blockReduce128(d * d) * (1.0f / 128.0f);
    float y = d * rsqrtf(var + LN_EPS) * gamma[c] + beta[c];
    g_h[(size_t)n * 128 + c] = fmaxf(y, 0.0f) * g_escale;
}

// ---------------- output: LN per row then mean over nodes ----------------
__global__ void k_zero_out(float* out) { out[threadIdx.x] = 0.0f; }

__global__ void k_out_reduce(const float* __restrict__ tmp,
                             const float* __restrict__ gamma,
                             const float* __restrict__ beta,
                             float* __restrict__ out, int N) {
    int c = threadIdx.x;
    int r0 = blockIdx.x * 64;
    float partial = 0.0f;
    for (int r = r0; r < r0 + 64; r++) {
        if (r >= N) break;
        float v = tmp[(size_t)r * 128 + c];
        float mu = blockReduce128(v) * (1.0f / 128.0f);
        float d = v - mu;
        float var = blockReduce128(d * d) * (1.0f / 128.0f);
        partial += d * rsqrtf(var + LN_EPS) * gamma[c] + beta[c];
    }
    atomicAdd(&out[c], partial / (float)N);
}

// ---------------- host orchestration ----------------
extern "C" void kernel_launch(void* const* d_in, const int* in_sizes, int n_in,
                              void* d_out, int out_size) {
    const float* x        = (const float*)d_in[0];
    const int*   ei       = (const int*)  d_in[1];
    const float* Wi       = (const float*)d_in[2];
    const float* bi       = (const float*)d_in[3];
    const float* ln_in_g  = (const float*)d_in[4];
    const float* ln_in_b  = (const float*)d_in[5];
    const float* meth     = (const float*)d_in[6];
    const float* hist     = (const float*)d_in[7];
    const float* gcn_w    = (const float*)d_in[8];
    const float* gcn_b    = (const float*)d_in[9];
    const float* ln_g     = (const float*)d_in[10];
    const float* ln_b     = (const float*)d_in[11];
    const float* gate_w   = (const float*)d_in[12];
    const float* gate_b   = (const float*)d_in[13];
    const float* res_w    = (const float*)d_in[14];
    const float* log_d    = (const float*)d_in[15];
    const float* Wo       = (const float*)d_in[16];
    const float* bo       = (const float*)d_in[17];
    const float* ln_out_g = (const float*)d_in[18];
    const float* ln_out_b = (const float*)d_in[19];
    float* out = (float*)d_out;

    int N = in_sizes[0] / 64;   // 20000
    int E = in_sizes[1] / 2;    // 320000
    const int* e_row = ei;
    const int* e_col = ei + E;

    float *p_h, *p_hh, *p_hc, *p_hn, *p_tmp;
    cudaGetSymbolAddress((void**)&p_h,  g_h);
    cudaGetSymbolAddress((void**)&p_hh, g_hh);
    cudaGetSymbolAddress((void**)&p_hc, g_hc);
    cudaGetSymbolAddress((void**)&p_hn, g_hn);
    cudaGetSymbolAddress((void**)&p_tmp,g_tmp);

    cudaFuncSetAttribute(tensor_mm, cudaFuncAttributeMaxDynamicSharedMemorySize, SMM_BYTES);

    int gbt = (N + TM - 1) / TM;     // 79 blocks -> single wave
    int eg = (E + 255) / 256;
    int ng = (N + 255) / 256;

    // --- graph preprocessing (every replay; cheap) ---
    k_zero_cnt<<<ng, 256>>>(N);
    k_deg<<<eg, 256>>>(e_col, E);
    k_dis<<<ng, 256>>>(N);
    k_scan<<<1, 1024>>>(N);
    k_scatter<<<eg, 256>>>(e_row, e_col, E);
    k_scalars<<<1, 128>>>(meth, hist, log_d);

    // --- input projection: h = relu(LN(x@Wi + bi)) * escale ---
    tensor_mm<<<gbt, 512, SMM_BYTES>>>(x, nullptr, Wi, bi, p_tmp, N, 64, 64, 0, 0, nullptr, nullptr);
    k_ln_relu_scale<<<N, 128>>>(p_tmp, ln_in_g, ln_in_b);

    // --- 19 RK4 steps, 4 f-evals each ---
    for (int step = 0; step < 19; step++) {
        for (int st = 0; st < 4; st++) {
            const float* fin = (st == 0) ? p_h : p_hh;
            // GCN layer 0
            tensor_mm<<<gbt, 512, SMM_BYTES>>>(fin, nullptr, gcn_w, nullptr, p_tmp, N, 128, 128, 0, 0, nullptr, nullptr);
            agg_ln_kernel<<<N, 128>>>(p_tmp, gcn_b, ln_g, ln_b, p_hc);
            // GCN layer 1 + gate
            tensor_mm<<<gbt, 512, SMM_BYTES>>>(p_hc, nullptr, gcn_w + 128*128, nullptr, p_tmp, N, 128, 128, 0, 0, nullptr, nullptr);
            agg_ln_kernel<<<N, 128>>>(p_tmp, gcn_b + 128, ln_g + 128, ln_b + 128, p_hn);
            tensor_mm<<<gbt, 512, SMM_BYTES>>>(p_hc, p_hn, gate_w, gate_b, p_hc, N, 256, 128, 1, 0, nullptr, nullptr);
            // GCN layer 2 + gate + fused RK stage
            tensor_mm<<<gbt, 512, SMM_BYTES>>>(p_hc, nullptr, gcn_w + 2*128*128, nullptr, p_tmp, N, 128, 128, 0, 0, nullptr, nullptr);
            agg_ln_kernel<<<N, 128>>>(p_tmp, gcn_b + 256, ln_g + 256, ln_b + 256, p_hn);
            tensor_mm<<<gbt, 512, SMM_BYTES>>>(p_hc, p_hn, gate_w, gate_b, nullptr, N, 256, 128, 2, st, fin, res_w);
        }
    }

    // --- output projection + LN + global mean pool ---
    tensor_mm<<<gbt, 512, SMM_BYTES>>>(p_h, nullptr, Wo, bo, p_tmp, N, 128, 128, 0, 0, nullptr, nullptr);
    k_zero_out<<<1, 128>>>(out);
    k_out_reduce<<<(N + 63) / 64, 128>>>(p_tmp, ln_out_g, ln_out_b, out, N);
}